// round 10
// baseline (speedup 1.0000x reference)
#include <cuda_runtime.h>

// LIF scan, bit-faithful to the reference per-op rounding:
//   v_euler = v + ((-v + 3000*I) / 150) * 0.01   (each op RN-rounded; div via
//   Markstein 3-op refinement == div.rn.f32)
//   v = (v >= 15) ? 0 : v_euler ; v = (v >= 15) ? 30 : v
// Carried-predicate invariant: entering any step v is exactly 30 or < 15, so the
// reset predicate equals the previous step's spike predicate (one compare/step).
//
// R10: UNROLL_T=13 with INTERLEAVED prefetch — one next-chunk load issued per
// current-chunk compute+store, instead of batching all 13 loads up front.
// Goal: smooth the read/write burst alternation that drives the sustained-replay
// penalty (bench-vs-ncu gap: U12 +2.8us, U13 +6.1us, U14 +12.9us, U20 +17.5us)
// while keeping steady-state MLP ~13/warp. Shape otherwise frozen: float2 lanes,
// 1024x64 (13.8 warps/SM), streaming cache ops. 1000 = 76*13 + 12.

#define UNROLL_T 13
#define TAIL_T 12
#define T_STEPS 1000
#define N_NEUR 131072
#define N2 (N_NEUR / 2)  // float2 pairs per timestep = 65536

__device__ __forceinline__ void lif_step(float& v, bool& p, float I) {
    const float y = (float)(1.0 / 150.0);        // RN(1/150)
    float pr  = __fmul_rn(I, 3000.0f);
    float num = __fadd_rn(pr, -v);
    float q0  = __fmul_rn(num, y);
    float rr  = __fmaf_rn(q0, -150.0f, num);     // exact remainder (FMA)
    float q   = __fmaf_rn(rr, y, q0);            // correctly rounded num/150
    float dv  = __fmul_rn(q, 0.01f);
    float ve  = __fadd_rn(v, dv);
    bool spike = (ve >= 15.0f) && (!p);
    float tv = p ? 0.0f : ve;
    v = spike ? 30.0f : tv;
    p = spike;
}

__global__ void __launch_bounds__(64)
lif_kernel_fixed(const float2* __restrict__ stim, float2* __restrict__ out) {
    const int idx = blockIdx.x * 64 + threadIdx.x;     // pair index 0..N2-1
    const float2* __restrict__ sp = stim + idx;

    float v0 = 0.0f, v1 = 0.0f;
    bool p0 = false, p1 = false;

    const size_t row   = (size_t)N2;                   // pairs per timestep
    const size_t chunk = (size_t)UNROLL_T * row;

    float2 buf[UNROLL_T];
    #pragma unroll
    for (int u = 0; u < UNROLL_T; u++) buf[u] = __ldcs(sp + (size_t)u * row);

    const float2* __restrict__ ld = sp + chunk;
    float2* __restrict__ st = out + idx;

    // 76 full chunks total; 75 loop iterations, each with 1:1 interleaved
    // next-chunk load + current-chunk compute/store.
    for (int c = 0; c < 75; c++) {
        float2 nbuf[UNROLL_T];
        #pragma unroll
        for (int u = 0; u < UNROLL_T; u++) {
            nbuf[u] = __ldcs(ld + (size_t)u * row);    // next-chunk load u
            lif_step(v0, p0, buf[u].x);                // current-chunk step u
            lif_step(v1, p1, buf[u].y);
            __stcs(st + (size_t)u * row, make_float2(v0, v1));
        }
        #pragma unroll
        for (int u = 0; u < UNROLL_T; u++) buf[u] = nbuf[u];
        ld += chunk;
        st += chunk;
    }

    // buf holds chunk 75 (steps 975..987); ld points at step 988. Interleave
    // the 12-step tail prefetch into the last full chunk's compute.
    float2 tbuf[TAIL_T];
    #pragma unroll
    for (int u = 0; u < UNROLL_T; u++) {
        if (u < TAIL_T) tbuf[u] = __ldcs(ld + (size_t)u * row);
        lif_step(v0, p0, buf[u].x);
        lif_step(v1, p1, buf[u].y);
        __stcs(st + (size_t)u * row, make_float2(v0, v1));
    }
    st += chunk;

    // Tail: steps 988..999
    #pragma unroll
    for (int u = 0; u < TAIL_T; u++) {
        lif_step(v0, p0, tbuf[u].x);
        lif_step(v1, p1, tbuf[u].y);
        __stcs(st + (size_t)u * row, make_float2(v0, v1));
    }
}

// Generic fallback (any N, T=1000 assumed) — correctness path for odd shapes.
__global__ void lif_kernel_generic(const float* __restrict__ stim,
                                   float* __restrict__ out, int N, int T) {
    int n = blockIdx.x * blockDim.x + threadIdx.x;
    if (n >= N) return;
    float v = 0.0f;
    bool p = false;
    for (int t = 0; t < T; t++) {
        lif_step(v, p, stim[(size_t)t * N + n]);
        out[(size_t)t * N + n] = v;
    }
}

extern "C" void kernel_launch(void* const* d_in, const int* in_sizes, int n_in,
                              void* d_out, int out_size) {
    const float* stim = (const float*)d_in[0];
    float* out = (float*)d_out;

    if (in_sizes[0] == T_STEPS * N_NEUR && out_size == T_STEPS * N_NEUR) {
        // 65536 pairs / 64 threads = 1024 blocks (one wave on 148 SMs)
        lif_kernel_fixed<<<N2 / 64, 64>>>((const float2*)stim, (float2*)out);
    } else {
        int T = 1000;
        int N = in_sizes[0] / T;
        int threads = 128;
        int blocks = (N + threads - 1) / threads;
        lif_kernel_generic<<<blocks, threads>>>(stim, out, N, T);
    }
}

// round 11
// speedup vs baseline: 1.0243x; 1.0243x over previous
#include <cuda_runtime.h>

// LIF scan, bit-faithful to the reference per-op rounding:
//   v_euler = v + ((-v + 3000*I) / 150) * 0.01   (each op RN-rounded; div via
//   Markstein 3-op refinement == div.rn.f32)
//   v = (v >= 15) ? 0 : v_euler ; v = (v >= 15) ? 30 : v
// Carried-predicate invariant: entering any step v is exactly 30 or < 15, so the
// reset predicate equals the previous step's spike predicate (one compare/step).
//
// R11: UNROLL_T=13 with TWO-GROUP prefetch (7+6): batch 7 next-chunk loads,
// compute/store 7 current steps, batch remaining 6 loads, compute/store 6.
// Keeps the batched-MLP latency coverage that full 1:1 interleave (R10) lost,
// while halving read-burst length vs R9's all-up-front batch (sustained-replay
// gap: U12 +2.8us, U13-batched +6.1us, U13-interleaved lost coverage entirely).
// Shape frozen: float2 lanes, 1024x64 (13.8 warps/SM), streaming cache ops.
// 1000 = 76*13 + 12.

#define UNROLL_T 13
#define SPLIT_U 7
#define TAIL_T 12
#define T_STEPS 1000
#define N_NEUR 131072
#define N2 (N_NEUR / 2)  // float2 pairs per timestep = 65536

__device__ __forceinline__ void lif_step(float& v, bool& p, float I) {
    const float y = (float)(1.0 / 150.0);        // RN(1/150)
    float pr  = __fmul_rn(I, 3000.0f);
    float num = __fadd_rn(pr, -v);
    float q0  = __fmul_rn(num, y);
    float rr  = __fmaf_rn(q0, -150.0f, num);     // exact remainder (FMA)
    float q   = __fmaf_rn(rr, y, q0);            // correctly rounded num/150
    float dv  = __fmul_rn(q, 0.01f);
    float ve  = __fadd_rn(v, dv);
    bool spike = (ve >= 15.0f) && (!p);
    float tv = p ? 0.0f : ve;
    v = spike ? 30.0f : tv;
    p = spike;
}

__global__ void __launch_bounds__(64)
lif_kernel_fixed(const float2* __restrict__ stim, float2* __restrict__ out) {
    const int idx = blockIdx.x * 64 + threadIdx.x;     // pair index 0..N2-1
    const float2* __restrict__ sp = stim + idx;

    float v0 = 0.0f, v1 = 0.0f;
    bool p0 = false, p1 = false;

    const size_t row   = (size_t)N2;                   // pairs per timestep
    const size_t chunk = (size_t)UNROLL_T * row;

    float2 buf[UNROLL_T];
    #pragma unroll
    for (int u = 0; u < UNROLL_T; u++) buf[u] = __ldcs(sp + (size_t)u * row);

    const float2* __restrict__ ld = sp + chunk;
    float2* __restrict__ st = out + idx;

    // 76 full chunks total; 75 loop iterations with two-group prefetch.
    for (int c = 0; c < 75; c++) {
        float2 nbuf[UNROLL_T];
        // Group A: 7 next-chunk loads, then 7 current-chunk steps
        #pragma unroll
        for (int u = 0; u < SPLIT_U; u++) nbuf[u] = __ldcs(ld + (size_t)u * row);
        #pragma unroll
        for (int u = 0; u < SPLIT_U; u++) {
            lif_step(v0, p0, buf[u].x);
            lif_step(v1, p1, buf[u].y);
            __stcs(st + (size_t)u * row, make_float2(v0, v1));
        }
        // Group B: remaining 6 loads, then remaining 6 steps
        #pragma unroll
        for (int u = SPLIT_U; u < UNROLL_T; u++) nbuf[u] = __ldcs(ld + (size_t)u * row);
        #pragma unroll
        for (int u = SPLIT_U; u < UNROLL_T; u++) {
            lif_step(v0, p0, buf[u].x);
            lif_step(v1, p1, buf[u].y);
            __stcs(st + (size_t)u * row, make_float2(v0, v1));
        }
        #pragma unroll
        for (int u = 0; u < UNROLL_T; u++) buf[u] = nbuf[u];
        ld += chunk;
        st += chunk;
    }

    // buf holds chunk 75 (steps 975..987); ld points at step 988. Prefetch tail
    // in two groups interleaved with the last full chunk's compute.
    float2 tbuf[TAIL_T];
    #pragma unroll
    for (int u = 0; u < SPLIT_U; u++) tbuf[u] = __ldcs(ld + (size_t)u * row);
    #pragma unroll
    for (int u = 0; u < SPLIT_U; u++) {
        lif_step(v0, p0, buf[u].x);
        lif_step(v1, p1, buf[u].y);
        __stcs(st + (size_t)u * row, make_float2(v0, v1));
    }
    #pragma unroll
    for (int u = SPLIT_U; u < TAIL_T; u++) tbuf[u] = __ldcs(ld + (size_t)u * row);
    #pragma unroll
    for (int u = SPLIT_U; u < UNROLL_T; u++) {
        lif_step(v0, p0, buf[u].x);
        lif_step(v1, p1, buf[u].y);
        __stcs(st + (size_t)u * row, make_float2(v0, v1));
    }
    st += chunk;

    // Tail: steps 988..999
    #pragma unroll
    for (int u = 0; u < TAIL_T; u++) {
        lif_step(v0, p0, tbuf[u].x);
        lif_step(v1, p1, tbuf[u].y);
        __stcs(st + (size_t)u * row, make_float2(v0, v1));
    }
}

// Generic fallback (any N, T=1000 assumed) — correctness path for odd shapes.
__global__ void lif_kernel_generic(const float* __restrict__ stim,
                                   float* __restrict__ out, int N, int T) {
    int n = blockIdx.x * blockDim.x + threadIdx.x;
    if (n >= N) return;
    float v = 0.0f;
    bool p = false;
    for (int t = 0; t < T; t++) {
        lif_step(v, p, stim[(size_t)t * N + n]);
        out[(size_t)t * N + n] = v;
    }
}

extern "C" void kernel_launch(void* const* d_in, const int* in_sizes, int n_in,
                              void* d_out, int out_size) {
    const float* stim = (const float*)d_in[0];
    float* out = (float*)d_out;

    if (in_sizes[0] == T_STEPS * N_NEUR && out_size == T_STEPS * N_NEUR) {
        // 65536 pairs / 64 threads = 1024 blocks (one wave on 148 SMs)
        lif_kernel_fixed<<<N2 / 64, 64>>>((const float2*)stim, (float2*)out);
    } else {
        int T = 1000;
        int N = in_sizes[0] / T;
        int threads = 128;
        int blocks = (N + threads - 1) / threads;
        lif_kernel_generic<<<blocks, threads>>>(stim, out, N, T);
    }
}